// round 12
// baseline (speedup 1.0000x reference)
#include <cuda_runtime.h>
#include <cuda_fp16.h>
#include <cstdint>

#define C_DIM  256
#define NPIX   4096
#define BATCH  16
#define SPLITK 4

// ---------------------------------------------------------------------------
// Scratch (__device__ globals; allocation-free rule)
// ---------------------------------------------------------------------------
__device__ __align__(16) __half g_Wqkv[3 * C_DIM * C_DIM];   // fp16 packed [768][256]
__device__ __align__(16) __half g_Wo  [C_DIM * C_DIM];
__device__ __align__(16) __half g_x   [BATCH * C_DIM * NPIX];   // 32 MB
__device__ __align__(16) __half g_phi_q[BATCH * C_DIM * NPIX];
__device__ __align__(16) __half g_phi_k[BATCH * C_DIM * NPIX];
__device__ __align__(16) __half g_phi_v[BATCH * C_DIM * NPIX];
__device__ float  g_qvp[SPLITK * BATCH * C_DIM * C_DIM];        // fp32 partials
__device__ __align__(16) __half g_qv  [BATCH * C_DIM * C_DIM];
__device__ __align__(16) __half g_m   [BATCH * C_DIM * C_DIM];

__device__ __forceinline__ float phi_f(float x) {
    return x > 0.0f ? x + 1.0f : __expf(x);
}

__device__ __forceinline__ void mma_f16(float c[4], const uint32_t a[4],
                                        uint32_t b0, uint32_t b1) {
    asm volatile(
        "mma.sync.aligned.m16n8k16.row.col.f32.f16.f16.f32 "
        "{%0,%1,%2,%3},{%4,%5,%6,%7},{%8,%9},{%0,%1,%2,%3};"
        : "+f"(c[0]), "+f"(c[1]), "+f"(c[2]), "+f"(c[3])
        : "r"(a[0]), "r"(a[1]), "r"(a[2]), "r"(a[3]), "r"(b0), "r"(b1));
}

__device__ __forceinline__ void ldsm_x4(uint32_t& r0, uint32_t& r1,
                                        uint32_t& r2, uint32_t& r3, uint32_t addr) {
    asm volatile("ldmatrix.sync.aligned.m8n8.x4.shared.b16 {%0,%1,%2,%3}, [%4];"
                 : "=r"(r0), "=r"(r1), "=r"(r2), "=r"(r3) : "r"(addr));
}
__device__ __forceinline__ void ldsm_x4_t(uint32_t& r0, uint32_t& r1,
                                          uint32_t& r2, uint32_t& r3, uint32_t addr) {
    asm volatile("ldmatrix.sync.aligned.m8n8.x4.trans.shared.b16 {%0,%1,%2,%3}, [%4];"
                 : "=r"(r0), "=r"(r1), "=r"(r2), "=r"(r3) : "r"(addr));
}

__device__ __forceinline__ void cpa16(uint32_t saddr, const void* gptr) {
    asm volatile("cp.async.cg.shared.global [%0], [%1], 16;"
                 :: "r"(saddr), "l"(gptr));
}
__device__ __forceinline__ void cpa_commit() {
    asm volatile("cp.async.commit_group;");
}
template<int N>
__device__ __forceinline__ void cpa_wait() {
    asm volatile("cp.async.wait_group %0;" :: "n"(N));
}

// ---------------------------------------------------------------------------
// fp16 GEMM core: BM=64, BN=128, BK=32, 128 threads = 4 warps (2m x 2n),
// warp tile 32x64 -> 2 m-subtiles x 8 n-subtiles of m16n8k16.
// 3-stage cp.async pipeline (2 iters of load slack), static 45KB smem,
// ldmatrix fragment loads with interleaved B consume (low reg pressure).
// BT=false: B is [K][N] fp16 (pre-offset by n0 cols).
// BT=true : B is [N][K] fp16 (pre-offset by n0 rows).
// ---------------------------------------------------------------------------
#define NSTAGE 3
#define LDA_H 40                         // halves: 32 + 8 pad (80B rows, conflict-free)
#define LDB_H 136                        // halves: 128 + 8 pad (272B rows, NN)
#define A_BYTES (64 * LDA_H * 2)         // 5120
#define B_BYTES (128 * LDA_H * 2)        // 10240 (NN uses 32*136*2 = 8704)
#define STAGE_BYTES (A_BYTES + B_BYTES)  // 15360
#define SMEM_BYTES (NSTAGE * STAGE_BYTES) // 46080 (static, <= 48KB, no opt-in)

template<bool BT>
__device__ __forceinline__ void gemm_core(const __half* __restrict__ A,
                                          const __half* __restrict__ B,
                                          int K, int lda, int ldb,
                                          float c[2][8][4], char* smem_raw)
{
    const uint32_t smem_u = (uint32_t)__cvta_generic_to_shared(smem_raw);

    const int tid  = threadIdx.x;
    const int lane = tid & 31;
    const int wid  = tid >> 5;           // 0..3
    const int wm   = (wid & 1) * 32;
    const int wn   = (wid >> 1) * 64;

    // ldmatrix lane decomposition
    const int lrow = lane & 7;
    const int sel  = lane >> 3;          // 0..3
    const int selr = (sel & 1) << 3;     // +8 rows
    const int selc = (sel >> 1) << 3;    // +8 k (or +8 n halves for NN)

    // cp.async per-thread coordinates
    const int ar  = tid >> 2;            // 0..31
    const int ac8 = (tid & 3) << 3;      // halves 0,8,16,24
    const int br  = tid >> 4;            // 0..7 (NN k rows, stride 8)
    const int bc8 = (tid & 15) << 3;     // halves 0..120

    const int niter = K >> 5;

    auto load_stage = [&](int s, int k0) {
        const uint32_t sa = smem_u + (uint32_t)(s * STAGE_BYTES);
        const uint32_t sb = sa + A_BYTES;
        // A: 64 rows x 32 halves -> 2 chunks/thread
#pragma unroll
        for (int p = 0; p < 2; p++) {
            const int r = ar + p * 32;
            cpa16(sa + (uint32_t)(r * LDA_H + ac8) * 2,
                  A + (size_t)r * lda + k0 + ac8);
        }
        if (BT) {
#pragma unroll
            for (int p = 0; p < 4; p++) {
                const int r = ar + p * 32;
                cpa16(sb + (uint32_t)(r * LDA_H + ac8) * 2,
                      B + (size_t)r * ldb + k0 + ac8);
            }
        } else {
#pragma unroll
            for (int p = 0; p < 4; p++) {
                const int r = br + p * 8;
                cpa16(sb + (uint32_t)(r * LDB_H + bc8) * 2,
                      B + (size_t)(k0 + r) * ldb + bc8);
            }
        }
        cpa_commit();
    };

    // prologue: fill NSTAGE-1 stages
    load_stage(0, 0);
    if (niter > 1) load_stage(1, 32);

    int s_cur = 0;
    for (int it = 0; it < niter; it++) {
        // issue load for stage it+2 (keeps 3 groups in flight)
        if (it + NSTAGE - 1 < niter) {
            int s_nxt = s_cur + 2; if (s_nxt >= NSTAGE) s_nxt -= NSTAGE;
            load_stage(s_nxt, (it + NSTAGE - 1) << 5);
            cpa_wait<NSTAGE - 1>();
        } else if (it + NSTAGE - 2 < niter) {
            cpa_wait<1>();
        } else {
            cpa_wait<0>();
        }
        __syncthreads();

        const uint32_t sa = smem_u + (uint32_t)(s_cur * STAGE_BYTES);
        const uint32_t sb = sa + A_BYTES;

#pragma unroll
        for (int ks = 0; ks < 32; ks += 16) {
            // ---- A fragments: 2 x ldmatrix.x4 ----
            uint32_t a[2][4];
#pragma unroll
            for (int mi = 0; mi < 2; mi++) {
                const int row = wm + mi * 16 + selr + lrow;
                ldsm_x4(a[mi][0], a[mi][1], a[mi][2], a[mi][3],
                        sa + (uint32_t)(row * LDA_H + ks + selc) * 2);
            }
            // ---- B fragments interleaved with MMA (low live regs) ----
#pragma unroll
            for (int p = 0; p < 4; p++) {
                const int nb = wn + p * 16;
                uint32_t r0, r1, r2, r3;
                if (BT) {
                    const int row = nb + selr + lrow;
                    ldsm_x4(r0, r1, r2, r3,
                            sb + (uint32_t)(row * LDA_H + ks + selc) * 2);
                    // pairs: (r0,r2) = ni 2p, (r1,r3) = ni 2p+1
                    mma_f16(c[0][2*p],   a[0], r0, r2);
                    mma_f16(c[1][2*p],   a[1], r0, r2);
                    mma_f16(c[0][2*p+1], a[0], r1, r3);
                    mma_f16(c[1][2*p+1], a[1], r1, r3);
                } else {
                    const int krow = ks + selr + lrow;
                    ldsm_x4_t(r0, r1, r2, r3,
                              sb + (uint32_t)(krow * LDB_H + nb + selc) * 2);
                    // pairs: (r0,r1) = ni 2p, (r2,r3) = ni 2p+1
                    mma_f16(c[0][2*p],   a[0], r0, r1);
                    mma_f16(c[1][2*p],   a[1], r0, r1);
                    mma_f16(c[0][2*p+1], a[0], r2, r3);
                    mma_f16(c[1][2*p+1], a[1], r2, r3);
                }
            }
        }
        __syncthreads();
        if (++s_cur == NSTAGE) s_cur = 0;
    }
}

#define ACC_INIT(c)                                   \
    _Pragma("unroll")                                 \
    for (int mi = 0; mi < 2; mi++)                    \
        _Pragma("unroll")                             \
        for (int ni = 0; ni < 8; ni++)                \
            _Pragma("unroll")                         \
            for (int e = 0; e < 4; e++) c[mi][ni][e] = 0.0f;

#define EPILOGUE_COORDS                               \
    const int lane = threadIdx.x & 31;                \
    const int wid  = threadIdx.x >> 5;                \
    const int g    = lane >> 2;                       \
    const int t    = lane & 3;                        \
    const int wm   = (wid & 1) * 32;                  \
    const int wn   = (wid >> 1) * 64;

// ---------------------------------------------------------------------------
// Prep kernels: fp32 -> fp16
// ---------------------------------------------------------------------------
__global__ void pack_w(const float* __restrict__ q, const float* __restrict__ k,
                       const float* __restrict__ v, const float* __restrict__ o)
{
    const int i = blockIdx.x * 256 + threadIdx.x;
    g_Wqkv[i]                     = __float2half_rn(q[i]);
    g_Wqkv[C_DIM * C_DIM + i]     = __float2half_rn(k[i]);
    g_Wqkv[2 * C_DIM * C_DIM + i] = __float2half_rn(v[i]);
    g_Wo[i]                       = __float2half_rn(o[i]);
}

__global__ void cvt_x_kernel(const float* __restrict__ x)
{
    const size_t i = ((size_t)blockIdx.x * 256 + threadIdx.x) * 4;
    const float4 v = *(const float4*)(x + i);
    __half2 h0 = __floats2half2_rn(v.x, v.y);
    __half2 h1 = __floats2half2_rn(v.z, v.w);
    uint2 u;
    u.x = *(uint32_t*)&h0;
    u.y = *(uint32_t*)&h1;
    *(uint2*)(g_x + i) = u;
}

// ---------------------------------------------------------------------------
// A: Wqkv[768x256] @ x[b][256x4096] -> phi -> fp16 -> g_phi_{q,k,v}
// grid (32, 12, 16), 128 threads
// ---------------------------------------------------------------------------
__global__ void __launch_bounds__(128, 4)
qkv_kernel()
{
    __shared__ __align__(16) char smem[SMEM_BYTES];
    const int b  = blockIdx.z;
    const int m0 = blockIdx.y * 64;      // 0..704 within [768]
    const int n0 = blockIdx.x * 128;

    const __half* A = g_Wqkv + (size_t)m0 * C_DIM;
    const __half* B = g_x + (size_t)b * C_DIM * NPIX + n0;

    float c[2][8][4];
    ACC_INIT(c)
    gemm_core<false>(A, B, C_DIM, C_DIM, NPIX, c, smem);

    __half* bufs[3] = {g_phi_q, g_phi_k, g_phi_v};
    __half* Ob = bufs[m0 >> 8] + (size_t)b * C_DIM * NPIX;
    const int rowc0 = m0 & 255;

    EPILOGUE_COORDS
#pragma unroll
    for (int mi = 0; mi < 2; mi++)
#pragma unroll
        for (int ni = 0; ni < 8; ni++) {
            const int col = n0 + wn + ni * 8 + 2 * t;
#pragma unroll
            for (int h = 0; h < 2; h++) {
                const int row = rowc0 + wm + mi * 16 + g + h * 8;
                __half2 o = __floats2half2_rn(phi_f(c[mi][ni][2 * h + 0]),
                                              phi_f(c[mi][ni][2 * h + 1]));
                *(uint32_t*)(Ob + (size_t)row * NPIX + col) = *(uint32_t*)&o;
            }
        }
}

// ---------------------------------------------------------------------------
// B: split-K qv partials: g_qvp[b*4+sp] = phi_q[b][:, sp*1024:+1024] @ phi_v^T
// grid (2, 4, 64), 128 threads
// ---------------------------------------------------------------------------
__global__ void __launch_bounds__(128, 4)
qv_kernel()
{
    __shared__ __align__(16) char smem[SMEM_BYTES];
    const int z  = blockIdx.z;
    const int b  = z >> 2;
    const int sp = z & 3;
    const int m0 = blockIdx.y * 64;
    const int n0 = blockIdx.x * 128;
    const int kofs = sp * (NPIX / SPLITK);

    const __half* A = g_phi_q + (size_t)b * C_DIM * NPIX + (size_t)m0 * NPIX + kofs;
    const __half* B = g_phi_v + (size_t)b * C_DIM * NPIX + (size_t)n0 * NPIX + kofs;

    float c[2][8][4];
    ACC_INIT(c)
    gemm_core<true>(A, B, NPIX / SPLITK, NPIX, NPIX, c, smem);

    float* Cb = g_qvp + (size_t)z * C_DIM * C_DIM;

    EPILOGUE_COORDS
#pragma unroll
    for (int mi = 0; mi < 2; mi++)
#pragma unroll
        for (int ni = 0; ni < 8; ni++) {
            const int col = n0 + wn + ni * 8 + 2 * t;
#pragma unroll
            for (int h = 0; h < 2; h++) {
                const int row = m0 + wm + mi * 16 + g + h * 8;
                float2 o;
                o.x = c[mi][ni][2 * h + 0];
                o.y = c[mi][ni][2 * h + 1];
                *(float2*)(Cb + (size_t)row * C_DIM + col) = o;
            }
        }
}

// Deterministic fixed-order reduction -> fp16
__global__ void qv_reduce()
{
    const int j = blockIdx.x * 256 + threadIdx.x;
    const int b = j >> 16;
    const int i = j & 65535;
    const float* p = g_qvp + (size_t)b * SPLITK * C_DIM * C_DIM + i;
    float s = 0.0f;
#pragma unroll
    for (int sp = 0; sp < SPLITK; sp++) s += p[(size_t)sp * C_DIM * C_DIM];
    g_qv[j] = __float2half_rn(s);
}

// ---------------------------------------------------------------------------
// C: m[b] = Wo @ qv[b]   (NN, 256^3) -> fp16
// grid (2, 4, 16)
// ---------------------------------------------------------------------------
__global__ void __launch_bounds__(128, 4)
wo_qv_kernel()
{
    __shared__ __align__(16) char smem[SMEM_BYTES];
    const int b  = blockIdx.z;
    const int m0 = blockIdx.y * 64;
    const int n0 = blockIdx.x * 128;

    const __half* A = g_Wo + (size_t)m0 * C_DIM;
    const __half* B = g_qv + (size_t)b * C_DIM * C_DIM + n0;

    float c[2][8][4];
    ACC_INIT(c)
    gemm_core<false>(A, B, C_DIM, C_DIM, C_DIM, c, smem);

    __half* Cb = g_m + (size_t)b * C_DIM * C_DIM;

    EPILOGUE_COORDS
#pragma unroll
    for (int mi = 0; mi < 2; mi++)
#pragma unroll
        for (int ni = 0; ni < 8; ni++) {
            const int col = n0 + wn + ni * 8 + 2 * t;
#pragma unroll
            for (int h = 0; h < 2; h++) {
                const int row = m0 + wm + mi * 16 + g + h * 8;
                __half2 o = __floats2half2_rn(c[mi][ni][2 * h + 0],
                                              c[mi][ni][2 * h + 1]);
                *(uint32_t*)(Cb + (size_t)row * C_DIM + col) = *(uint32_t*)&o;
            }
        }
}

// ---------------------------------------------------------------------------
// D: out[b] = m[b] @ phi_k[b] + bo   (NN, M=256, N=4096, K=256), fp32 out
// grid (32, 4, 16)
// ---------------------------------------------------------------------------
__global__ void __launch_bounds__(128, 4)
out_kernel(const float* __restrict__ bo, float* __restrict__ out)
{
    __shared__ __align__(16) char smem[SMEM_BYTES];
    const int b  = blockIdx.z;
    const int m0 = blockIdx.y * 64;
    const int n0 = blockIdx.x * 128;

    const __half* A = g_m + (size_t)b * C_DIM * C_DIM + (size_t)m0 * C_DIM;
    const __half* B = g_phi_k + (size_t)b * C_DIM * NPIX + n0;

    float c[2][8][4];
    ACC_INIT(c)
    gemm_core<false>(A, B, C_DIM, C_DIM, NPIX, c, smem);

    float* Ob = out + (size_t)b * C_DIM * NPIX;

    EPILOGUE_COORDS
#pragma unroll
    for (int mi = 0; mi < 2; mi++)
#pragma unroll
        for (int ni = 0; ni < 8; ni++) {
            const int col = n0 + wn + ni * 8 + 2 * t;
#pragma unroll
            for (int h = 0; h < 2; h++) {
                const int row = m0 + wm + mi * 16 + g + h * 8;
                const float bi = bo[row];
                float2 o;
                o.x = c[mi][ni][2 * h + 0] + bi;
                o.y = c[mi][ni][2 * h + 1] + bi;
                *(float2*)(Ob + (size_t)row * NPIX + col) = o;
            }
        }
}

// ---------------------------------------------------------------------------
// Launch (guard-safe: no attribute calls, static smem only)
// ---------------------------------------------------------------------------
extern "C" void kernel_launch(void* const* d_in, const int* in_sizes, int n_in,
                              void* d_out, int out_size)
{
    const float* x  = (const float*)d_in[0];
    const float* Wq = (const float*)d_in[1];
    const float* Wk = (const float*)d_in[2];
    const float* Wv = (const float*)d_in[3];
    const float* Wo = (const float*)d_in[4];
    const float* bo = (const float*)d_in[5];
    float* out = (float*)d_out;

    pack_w<<<C_DIM * C_DIM / 256, 256>>>(Wq, Wk, Wv, Wo);
    cvt_x_kernel<<<BATCH * C_DIM * NPIX / 1024, 256>>>(x);

    // A: QKV + phi — grid (32, 12, 16)
    qkv_kernel<<<dim3(NPIX / 128, 768 / 64, BATCH), 128>>>();

    // B: qv split-K partials — grid (2, 4, 64)
    qv_kernel<<<dim3(C_DIM / 128, C_DIM / 64, BATCH * SPLITK), 128>>>();
    qv_reduce<<<BATCH * C_DIM * C_DIM / 256, 256>>>();

    // C: m = Wo @ qv — grid (2, 4, 16)
    wo_qv_kernel<<<dim3(C_DIM / 128, C_DIM / 64, BATCH), 128>>>();

    // D: out = m @ phi_k + bo — grid (32, 4, 16)
    out_kernel<<<dim3(NPIX / 128, C_DIM / 64, BATCH), 128>>>(bo, out);
}